// round 3
// baseline (speedup 1.0000x reference)
#include <cuda_runtime.h>
#include <math.h>

#define BATCH 16
#define NCLS 80
#define NANCH 17064
#define TOPK 100
#define IMG_W_MAX 1023.0f
#define IMG_H_MAX 799.0f
#define NMS_THR 0.6f
#define CLS_OFF 4096.0f

#define NMS_TPB 512
#define PER 34            // ceil(17064/512) = 34 (512*34 = 17408)
#define PK ((PER + 3) / 4)

// ---------------- scratch (device globals; no allocation allowed) ------------
__device__ float  g_scores[BATCH * NANCH];
__device__ float4 g_boxes [BATCH * NANCH];   // original boxes (for output)
__device__ float4 g_oboxes[BATCH * NANCH];   // class-offset boxes (for IoU, ref-faithful rounding)
__device__ int    g_cls   [BATCH * NANCH];

__device__ __forceinline__ float sigmoidf_(float x) {
    return 1.0f / (1.0f + expf(-x));
}

// ---------------- decode: per-anchor score / class / box ---------------------
__global__ void decode_kernel(
    const float* __restrict__ c0, const float* __restrict__ c1,
    const float* __restrict__ c2, const float* __restrict__ c3,
    const float* __restrict__ c4,
    const float* __restrict__ b0, const float* __restrict__ b1,
    const float* __restrict__ b2, const float* __restrict__ b3,
    const float* __restrict__ b4,
    const float* __restrict__ t0, const float* __restrict__ t1,
    const float* __restrict__ t2, const float* __restrict__ t3,
    const float* __restrict__ t4)
{
    int idx = blockIdx.x * blockDim.x + threadIdx.x;
    if (idx >= BATCH * NANCH) return;
    int b = idx / NANCH;
    int n = idx - b * NANCH;

    int base, H, W, S;
    const float* cp; const float* bp; const float* tp;
    if (n < 12800)      { base = 0;     H = 100; W = 128; S = 8;   cp = c0; bp = b0; tp = t0; }
    else if (n < 16000) { base = 12800; H = 50;  W = 64;  S = 16;  cp = c1; bp = b1; tp = t1; }
    else if (n < 16800) { base = 16000; H = 25;  W = 32;  S = 32;  cp = c2; bp = b2; tp = t2; }
    else if (n < 17008) { base = 16800; H = 13;  W = 16;  S = 64;  cp = c3; bp = b3; tp = t3; }
    else                { base = 17008; H = 7;   W = 8;   S = 128; cp = c4; bp = b4; tp = t4; }

    int hw = n - base;
    int HW = H * W;

    float ctrn = sigmoidf_(tp[(size_t)b * HW + hw]);

    const float* cbase = cp + (size_t)b * NCLS * HW + hw;
    float best = -INFINITY;
    int bc = 0;
    for (int c = 0; c < NCLS; c++) {
        float comb = sigmoidf_(cbase[(size_t)c * HW]) * ctrn;
        if (comb > best) { best = comb; bc = c; }
    }
    float score = sqrtf(best);

    const float* bb = bp + (size_t)b * 4 * HW + hw;
    float l = bb[0]        * (float)S;
    float t = bb[HW]       * (float)S;
    float r = bb[2 * HW]   * (float)S;
    float d = bb[3 * HW]   * (float)S;

    float px = (float)((hw % W) * S + S / 2);
    float py = (float)((hw / W) * S + S / 2);

    float x1 = fminf(fmaxf(px - l, 0.0f), IMG_W_MAX);
    float y1 = fminf(fmaxf(py - t, 0.0f), IMG_H_MAX);
    float x2 = fminf(fmaxf(px + r, 0.0f), IMG_W_MAX);
    float y2 = fminf(fmaxf(py + d, 0.0f), IMG_H_MAX);

    float off = (float)bc * CLS_OFF;

    g_scores[idx] = score;
    g_cls[idx]    = bc;
    g_boxes[idx]  = make_float4(x1, y1, x2, y2);
    g_oboxes[idx] = make_float4(x1 + off, y1 + off, x2 + off, y2 + off);
}

// ---------------- class-aware greedy NMS, one block per image ----------------
__global__ void __launch_bounds__(NMS_TPB, 1)
nms_kernel(float* __restrict__ out, int out_size)
{
    const int b    = blockIdx.x;
    const int tid  = threadIdx.x;
    const int warp = tid >> 5;
    const int lane = tid & 31;

    const float*  Sg = g_scores + (size_t)b * NANCH;
    const int*    Cg = g_cls    + (size_t)b * NANCH;
    const float4* Bg = g_boxes  + (size_t)b * NANCH;
    const float4* Og = g_oboxes + (size_t)b * NANCH;

    // per-thread candidates, registers only (no spill: 34 + 9 + temps << 128)
    float    sc[PER];
    unsigned cls_pk[PK];
#pragma unroll
    for (int k = 0; k < PK; k++) cls_pk[k] = 0;
#pragma unroll
    for (int j = 0; j < PER; j++) {
        int g = tid + j * NMS_TPB;
        unsigned cb;
        if (g < NANCH) { sc[j] = Sg[g]; cb = (unsigned)Cg[g] & 0xFFu; }
        else           { sc[j] = -INFINITY; cb = 0xFFu; }
        cls_pk[j >> 2] |= cb << ((j & 3) * 8);
    }

    __shared__ float  s_val[16];
    __shared__ int    s_idx[16];
    __shared__ float4 s_box;          // offset box of selected (for IoU)
    __shared__ int    s_cls, s_sel;

    const int  dets_elems = BATCH * TOPK * 5;   // 8000
    const bool write_cls  = (out_size >= dets_elems + BATCH * TOPK);

    for (int it = 0; it < TOPK; it++) {
        // ---- local argmax (strict '>' keeps lowest global index on ties)
        float bv = sc[0];
        int   bi = tid;
#pragma unroll
        for (int j = 1; j < PER; j++) {
            int g = tid + j * NMS_TPB;
            if (sc[j] > bv) { bv = sc[j]; bi = g; }
        }
        // ---- warp reduce (tie -> lower global index)
#pragma unroll
        for (int off = 16; off; off >>= 1) {
            float ov = __shfl_down_sync(0xffffffffu, bv, off);
            int   oi = __shfl_down_sync(0xffffffffu, bi, off);
            if (ov > bv || (ov == bv && oi < bi)) { bv = ov; bi = oi; }
        }
        if (lane == 0) { s_val[warp] = bv; s_idx[warp] = bi; }
        __syncthreads();

        if (warp == 0) {
            float v  = (lane < 16) ? s_val[lane] : -INFINITY;
            int   gi = (lane < 16) ? s_idx[lane] : 0x7fffffff;
            // prefetch candidate data in parallel with the reduce (hides L2 latency)
            float4 ob = make_float4(0.f, 0.f, 0.f, 0.f);
            float4 rb = make_float4(0.f, 0.f, 0.f, 0.f);
            int    cc = 0;
            if (lane < 16) { ob = Og[gi]; rb = Bg[gi]; cc = Cg[gi]; }
            // reduce over 16 warp winners, carry source lane
            float rv = v; int ri = gi; int rl = lane;
#pragma unroll
            for (int off = 8; off; off >>= 1) {
                float ov = __shfl_down_sync(0xffffffffu, rv, off);
                int   oi = __shfl_down_sync(0xffffffffu, ri, off);
                int   ol = __shfl_down_sync(0xffffffffu, rl, off);
                if (ov > rv || (ov == rv && oi < ri)) { rv = ov; ri = oi; rl = ol; }
            }
            int   wl = __shfl_sync(0xffffffffu, rl, 0);
            float wv = __shfl_sync(0xffffffffu, rv, 0);
            int   wi = __shfl_sync(0xffffffffu, ri, 0);
            // pull winner's prefetched data from its lane
            float obx = __shfl_sync(0xffffffffu, ob.x, wl);
            float oby = __shfl_sync(0xffffffffu, ob.y, wl);
            float obz = __shfl_sync(0xffffffffu, ob.z, wl);
            float obw = __shfl_sync(0xffffffffu, ob.w, wl);
            float rbx = __shfl_sync(0xffffffffu, rb.x, wl);
            float rby = __shfl_sync(0xffffffffu, rb.y, wl);
            float rbz = __shfl_sync(0xffffffffu, rb.z, wl);
            float rbw = __shfl_sync(0xffffffffu, rb.w, wl);
            int   wcc = __shfl_sync(0xffffffffu, cc,   wl);
            if (lane == 0) {
                s_box = make_float4(obx, oby, obz, obw);
                s_cls = wcc;
                s_sel = wi;
                bool valid = (wv > -INFINITY);
                int row = b * TOPK + it;
                float* dr = out + (size_t)row * 5;
                if (valid) {
                    dr[0] = rbx; dr[1] = rby; dr[2] = rbz; dr[3] = rbw; dr[4] = wv;
                } else {
                    dr[0] = 0.0f; dr[1] = 0.0f; dr[2] = 0.0f; dr[3] = 0.0f; dr[4] = -1.0f;
                }
                if (write_cls)
                    out[dets_elems + row] = valid ? (float)wcc : -1.0f;
            }
        }
        __syncthreads();

        // ---- suppression (IoU on offset boxes — matches reference rounding exactly)
        const float4 bx  = s_box;
        const int    scl = s_cls;
        const int    sel = s_sel;
        const float  sa  = (bx.z - bx.x) * (bx.w - bx.y);
#pragma unroll
        for (int j = 0; j < PER; j++) {
            int g = tid + j * NMS_TPB;
            if (g == sel) { sc[j] = -INFINITY; continue; }
            int cj = (int)((cls_pk[j >> 2] >> ((j & 3) * 8)) & 0xFFu);
            if (cj != scl || sc[j] == -INFINITY) continue;
            float4 obb = Og[g];
            float xx1 = fmaxf(bx.x, obb.x);
            float yy1 = fmaxf(bx.y, obb.y);
            float xx2 = fminf(bx.z, obb.z);
            float yy2 = fminf(bx.w, obb.w);
            float inter = fmaxf(xx2 - xx1, 0.0f) * fmaxf(yy2 - yy1, 0.0f);
            float oa = (obb.z - obb.x) * (obb.w - obb.y);
            float iou = inter / (sa + oa - inter + 1e-9f);
            if (iou > NMS_THR) sc[j] = -INFINITY;
        }
    }
}

// ---------------- launch ------------------------------------------------------
extern "C" void kernel_launch(void* const* d_in, const int* in_sizes, int n_in,
                              void* d_out, int out_size)
{
    const float* c[5]; const float* bx[5]; const float* ct[5];

    // interleaved per level (cls_p3, box_p3, ctr_p3, ...) vs grouped; detect by size
    if (n_in >= 15 && in_sizes[1] == 819200) {
        for (int i = 0; i < 5; i++) {
            c[i]  = (const float*)d_in[3 * i + 0];
            bx[i] = (const float*)d_in[3 * i + 1];
            ct[i] = (const float*)d_in[3 * i + 2];
        }
    } else {
        for (int i = 0; i < 5; i++) {
            c[i]  = (const float*)d_in[i];
            bx[i] = (const float*)d_in[5 + i];
            ct[i] = (const float*)d_in[10 + i];
        }
    }
    float* out = (float*)d_out;

    int total = BATCH * NANCH;
    decode_kernel<<<(total + 255) / 256, 256>>>(
        c[0], c[1], c[2], c[3], c[4],
        bx[0], bx[1], bx[2], bx[3], bx[4],
        ct[0], ct[1], ct[2], ct[3], ct[4]);

    nms_kernel<<<BATCH, NMS_TPB>>>(out, out_size);
}